// round 16
// baseline (speedup 1.0000x reference)
#include <cuda_runtime.h>
#include <cuda_fp16.h>
#include <math.h>

#define NN 4096
#define EE 32768
#define ET (EE + NN)
#define HEADS1 8
#define HC1 4096
#define HC2 512
#define FC1_SPLITS 8
#define G2_SPLITS 4

// ---------------- scratch (device globals) ----------------
__device__ __half g_xh[NN * 128];
__device__ __half g_w1h[(size_t)128 * HC1];
__device__ __half g_w2h[(size_t)HC1 * HC2];
__device__ __half g_fw1h[(size_t)HC1 * 512];
__device__ __half g_h1h[(size_t)NN * HC1];
__device__ __half g_o1h[(size_t)NN * HC1];
__device__ __half g_h2h[NN * HC2];
__device__ __half g_o2h[NN * HC2];
__device__ float g_as[NN * HEADS1];
__device__ float g_ad[NN * HEADS1];
__device__ float g_was[HEADS1 * 128];
__device__ float g_wad[HEADS1 * 128];
__device__ float g_eexp[(size_t)ET * HEADS1];
__device__ int g_rowptr[NN + 1];
__device__ int g_eids[ET];
__device__ int g_srcv[ET];
__device__ int g_dstv[ET];
__device__ float g_fc1[512 * 512];
__device__ float g_fc2[512 * 128];
__device__ float g_fcp[FC1_SPLITS * 512 * 512];
__device__ float g_gp2[G2_SPLITS * NN * HC2];

// float buffer tags
#define B_FC1 0
#define B_FC2 1
#define B_FCP 2
#define B_GP2 3
__device__ __forceinline__ float* bufptr(int b) {
    switch (b) {
        case B_FC1: return g_fc1;
        case B_FC2: return g_fc2;
        case B_FCP: return g_fcp;
        default: return g_gp2;
    }
}
// half buffer tags
#define H_XH 0
#define H_W1 1
#define H_W2 2
#define H_FW 3
#define H_H1 4
#define H_O1 5
#define H_H2 6
#define H_O2 7
__device__ __forceinline__ __half* hbuf(int b) {
    switch (b) {
        case H_XH: return g_xh;
        case H_W1: return g_w1h;
        case H_W2: return g_w2h;
        case H_FW: return g_fw1h;
        case H_H1: return g_h1h;
        case H_O1: return g_o1h;
        case H_H2: return g_h2h;
        default: return g_o2h;
    }
}

// ------------- mma + ldmatrix + cp.async helpers -------------
__device__ __forceinline__ void mma_f16(float* d, unsigned a0, unsigned a1, unsigned a2,
                                        unsigned a3, unsigned b0, unsigned b1) {
    asm volatile(
        "mma.sync.aligned.m16n8k16.row.col.f32.f16.f16.f32 "
        "{%0,%1,%2,%3}, {%4,%5,%6,%7}, {%8,%9}, {%0,%1,%2,%3};\n"
        : "+f"(d[0]), "+f"(d[1]), "+f"(d[2]), "+f"(d[3])
        : "r"(a0), "r"(a1), "r"(a2), "r"(a3), "r"(b0), "r"(b1));
}
__device__ __forceinline__ void ldsm4(unsigned* r, const void* p) {
    unsigned a = (unsigned)__cvta_generic_to_shared(p);
    asm volatile("ldmatrix.sync.aligned.m8n8.x4.shared.b16 {%0,%1,%2,%3}, [%4];"
                 : "=r"(r[0]), "=r"(r[1]), "=r"(r[2]), "=r"(r[3]) : "r"(a));
}
__device__ __forceinline__ void ldsm4t(unsigned* r, const void* p) {
    unsigned a = (unsigned)__cvta_generic_to_shared(p);
    asm volatile("ldmatrix.sync.aligned.m8n8.x4.trans.shared.b16 {%0,%1,%2,%3}, [%4];"
                 : "=r"(r[0]), "=r"(r[1]), "=r"(r[2]), "=r"(r[3]) : "r"(a));
}
__device__ __forceinline__ void cpasync16(void* s, const void* g) {
    unsigned sa = (unsigned)__cvta_generic_to_shared(s);
    asm volatile("cp.async.ca.shared.global [%0], [%1], 16;\n" ::"r"(sa), "l"(g));
}
__device__ __forceinline__ void cp_commit() { asm volatile("cp.async.commit_group;\n"); }
__device__ __forceinline__ void cp_wait1() { asm volatile("cp.async.wait_group 1;\n"); }
__device__ __forceinline__ void cp_wait0() { asm volatile("cp.async.wait_group 0;\n"); }

// ---------------- fused one-block CSR builder ----------------
// detect dtype, convert to int32 (+self-loops), histogram, scan, scatter — one CTA.
__global__ __launch_bounds__(1024) void k_graph(const int* __restrict__ raw) {
    __shared__ int s_cnt[NN];     // 16KB: counts, later cursors
    __shared__ int s_scan[1024];  // 4KB
    __shared__ int s_flag;
    int t = threadIdx.x;

    // phase 0: dtype probe (odd words of first 8192 edges) + zero counts
    int acc = 0;
    for (int i = t; i < 8192; i += 1024) acc |= raw[2 * i + 1];
    for (int i = t; i < NN; i += 1024) s_cnt[i] = 0;
    if (t == 0) s_flag = 0;
    __syncthreads();
    if (acc) atomicOr(&s_flag, 1);
    __syncthreads();
    int f64 = (s_flag == 0);

    // phase 1: convert + histogram
    for (int i = t; i < ET; i += 1024) {
        int s, d;
        if (i < EE) {
            if (f64) {
                s = raw[2 * i];
                d = raw[2 * (EE + i)];
            } else {
                s = raw[i];
                d = raw[EE + i];
            }
        } else {
            s = d = i - EE;
        }
        g_srcv[i] = s;
        g_dstv[i] = d;
        atomicAdd(&s_cnt[d], 1);
    }
    __syncthreads();

    // phase 2: exclusive scan (4 counters per thread)
    int c0 = s_cnt[4 * t + 0];
    int c1 = s_cnt[4 * t + 1];
    int c2 = s_cnt[4 * t + 2];
    int c3 = s_cnt[4 * t + 3];
    int sum = c0 + c1 + c2 + c3;
    s_scan[t] = sum;
    __syncthreads();
    for (int off = 1; off < 1024; off <<= 1) {
        int v = (t >= off) ? s_scan[t - off] : 0;
        __syncthreads();
        s_scan[t] += v;
        __syncthreads();
    }
    int excl = s_scan[t] - sum;
    g_rowptr[4 * t + 0] = excl;
    g_rowptr[4 * t + 1] = excl + c0;
    g_rowptr[4 * t + 2] = excl + c0 + c1;
    g_rowptr[4 * t + 3] = excl + c0 + c1 + c2;
    if (t == 1023) g_rowptr[NN] = excl + sum;
    // reset counters -> cursors
    s_cnt[4 * t + 0] = excl;
    s_cnt[4 * t + 1] = excl + c0;
    s_cnt[4 * t + 2] = excl + c0 + c1;
    s_cnt[4 * t + 3] = excl + c0 + c1 + c2;
    __syncthreads();

    // phase 3: scatter (cursor = absolute position)
    for (int i = t; i < ET; i += 1024) {
        int d = g_dstv[i];
        int pos = atomicAdd(&s_cnt[d], 1);
        g_eids[pos] = i;
    }
}

// ---------------- merged fp32->fp16 converts (x, W1, W2, fc1w) ----------------
#define CVT_S0 (NN * 128)
#define CVT_S1 (128 * HC1)
#define CVT_S2 (HC1 * HC2)
#define CVT_S3 (HC1 * 512)
#define CVT_TOT (CVT_S0 + CVT_S1 + CVT_S2 + CVT_S3)
__global__ void k_cvt_all(const float* __restrict__ x, const float* __restrict__ w1,
                          const float* __restrict__ w2, const float* __restrict__ fw) {
    int gi = (blockIdx.x * blockDim.x + threadIdx.x) * 16;
    if (gi >= CVT_TOT) return;
    const float* src;
    __half* dst;
    int i = gi;
    if (i < CVT_S0) {
        src = x; dst = g_xh;
    } else if ((i -= CVT_S0) < CVT_S1) {
        src = w1; dst = g_w1h;
    } else if ((i -= CVT_S1) < CVT_S2) {
        src = w2; dst = g_w2h;
    } else {
        i -= CVT_S2;
        src = fw; dst = g_fw1h;
    }
#pragma unroll
    for (int u = 0; u < 2; u++) {
        float4 a = *(const float4*)&src[i + u * 8];
        float4 b = *(const float4*)&src[i + u * 8 + 4];
        __half2 h0 = __floats2half2_rn(a.x, a.y);
        __half2 h1 = __floats2half2_rn(a.z, a.w);
        __half2 h2 = __floats2half2_rn(b.x, b.y);
        __half2 h3 = __floats2half2_rn(b.z, b.w);
        *(uint4*)&dst[i + u * 8] = make_uint4(*(unsigned*)&h0, *(unsigned*)&h1,
                                              *(unsigned*)&h2, *(unsigned*)&h3);
    }
}

// ---------------- fp16 GEMM: K-step 32, ldmatrix frags ----------------
template <bool OUTH>
__global__ __launch_bounds__(128) void k_mm_h(int Atag, int Btag, int Ctag,
                                              int M, int N, int Kc, int lda, int ldbN) {
    const __half* Ag = hbuf(Atag);
    const __half* Bg = hbuf(Btag);
    int koff = blockIdx.z * Kc;
    __shared__ __half As[2][128][40];
    __shared__ __half Bs[2][32][136];
    int tid = threadIdx.x;
    int lane = tid & 31, wid = tid >> 5;
    int wm = (wid >> 1) * 64, wn = (wid & 1) * 64;
    int bm = blockIdx.y * 128, bn = blockIdx.x * 128;
    int g = lane >> 2, t = lane & 3;

    float acc[4][8][4];
#pragma unroll
    for (int i = 0; i < 4; i++)
#pragma unroll
        for (int j = 0; j < 8; j++)
#pragma unroll
            for (int r = 0; r < 4; r++) acc[i][j][r] = 0.f;

    const int NIT = Kc / 32;
    int l16 = lane & 15, lhi = lane >> 4;
#define LOADH(it, buf)                                                                   \
    {                                                                                    \
        int kt = koff + (it) * 32;                                                       \
        _Pragma("unroll") for (int i = 0; i < 4; i++) {                                  \
            int idx = tid + i * 128, r = idx >> 2, ch = idx & 3;                         \
            cpasync16(&As[buf][r][ch * 8], Ag + (size_t)(bm + r) * lda + kt + ch * 8);   \
        }                                                                                \
        _Pragma("unroll") for (int i = 0; i < 4; i++) {                                  \
            int idx = tid + i * 128, r = idx >> 4, ch = idx & 15;                        \
            cpasync16(&Bs[buf][r][ch * 8], Bg + (size_t)(kt + r) * ldbN + bn + ch * 8);  \
        }                                                                                \
    }

    LOADH(0, 0);
    cp_commit();

    for (int it = 0; it < NIT; it++) {
        int cb = it & 1;
        if (it + 1 < NIT) {
            LOADH(it + 1, cb ^ 1);
            cp_commit();
            cp_wait1();
        } else {
            cp_wait0();
        }
        __syncthreads();
#pragma unroll
        for (int ks = 0; ks < 2; ks++) {
            unsigned af[4][4], bf[4][4];
#pragma unroll
            for (int i = 0; i < 4; i++)
                ldsm4(af[i], &As[cb][wm + i * 16 + l16][ks * 16 + lhi * 8]);
#pragma unroll
            for (int j4 = 0; j4 < 4; j4++)
                ldsm4t(bf[j4], &Bs[cb][ks * 16 + l16][wn + j4 * 16 + lhi * 8]);
#pragma unroll
            for (int i = 0; i < 4; i++)
#pragma unroll
                for (int j4 = 0; j4 < 4; j4++) {
                    mma_f16(acc[i][2 * j4], af[i][0], af[i][1], af[i][2], af[i][3],
                            bf[j4][0], bf[j4][1]);
                    mma_f16(acc[i][2 * j4 + 1], af[i][0], af[i][1], af[i][2], af[i][3],
                            bf[j4][2], bf[j4][3]);
                }
        }
        __syncthreads();
    }
    if (OUTH) {
        __half* Ch = hbuf(Ctag);
#pragma unroll
        for (int i = 0; i < 4; i++) {
            int row = bm + wm + i * 16 + g;
#pragma unroll
            for (int j = 0; j < 8; j++) {
                int col = bn + wn + j * 8 + t * 2;
                *(__half2*)&Ch[(size_t)row * N + col] =
                    __floats2half2_rn(acc[i][j][0], acc[i][j][1]);
                *(__half2*)&Ch[(size_t)(row + 8) * N + col] =
                    __floats2half2_rn(acc[i][j][2], acc[i][j][3]);
            }
        }
    } else {
        float* C = bufptr(Ctag) + (size_t)blockIdx.z * M * N;
#pragma unroll
        for (int i = 0; i < 4; i++) {
            int row = bm + wm + i * 16 + g;
#pragma unroll
            for (int j = 0; j < 8; j++) {
                int col = bn + wn + j * 8 + t * 2;
                *(float2*)&C[(size_t)row * N + col] = make_float2(acc[i][j][0], acc[i][j][1]);
                *(float2*)&C[(size_t)(row + 8) * N + col] =
                    make_float2(acc[i][j][2], acc[i][j][3]);
            }
        }
    }
}

// ---------------- fc1 split-K reduce + bias + relu ----------------
__global__ void k_fcreduce(const float* __restrict__ bias) {
    int i = blockIdx.x * blockDim.x + threadIdx.x;
    if (i >= 512 * 512) return;
    float s = bias[i & 511];
#pragma unroll
    for (int p = 0; p < FC1_SPLITS; p++) s += g_fcp[p * 512 * 512 + i];
    g_fc1[i] = s > 0.f ? s : 0.f;
}

// ---------------- small GEMM with bias(+relu) (fc2, fp32 SIMT) ---------------
template <bool RELU>
__global__ __launch_bounds__(256) void k_gemm64(int Atag, const float* __restrict__ B,
                                                const float* __restrict__ bias, int Ctag,
                                                int M, int N, int K) {
    const float* A = bufptr(Atag);
    float* C = bufptr(Ctag);
    __shared__ float As[16][64];
    __shared__ float Bs[16][64];
    int tid = threadIdx.x;
    int tx = tid & 15, ty = tid >> 4;
    int bm = blockIdx.y * 64, bn = blockIdx.x * 64;
    float acc[4][4];
#pragma unroll
    for (int r = 0; r < 4; r++)
#pragma unroll
        for (int c = 0; c < 4; c++) acc[r][c] = 0.f;

    for (int kt = 0; kt < K; kt += 16) {
        {
            int arow = tid >> 2, ak4 = tid & 3;
            float4 va = *(const float4*)&A[(size_t)(bm + arow) * K + kt + ak4 * 4];
            As[ak4 * 4 + 0][arow] = va.x;
            As[ak4 * 4 + 1][arow] = va.y;
            As[ak4 * 4 + 2][arow] = va.z;
            As[ak4 * 4 + 3][arow] = va.w;
            int brow = tid >> 4, bc4 = tid & 15;
            float4 vb = *(const float4*)&B[(size_t)(kt + brow) * N + bn + bc4 * 4];
            *(float4*)&Bs[brow][bc4 * 4] = vb;
        }
        __syncthreads();
#pragma unroll
        for (int kk = 0; kk < 16; kk++) {
            float a[4], b[4];
            *(float4*)a = *(const float4*)&As[kk][ty * 4];
            *(float4*)b = *(const float4*)&Bs[kk][tx * 4];
#pragma unroll
            for (int r = 0; r < 4; r++)
#pragma unroll
                for (int c = 0; c < 4; c++) acc[r][c] += a[r] * b[c];
        }
        __syncthreads();
    }
#pragma unroll
    for (int r = 0; r < 4; r++) {
        int m = bm + ty * 4 + r;
#pragma unroll
        for (int c = 0; c < 4; c++) {
            int n = bn + tx * 4 + c;
            float v = acc[r][c] + bias[n];
            if (RELU) v = v > 0.f ? v : 0.f;
            C[(size_t)m * N + n] = v;
        }
    }
}

// ---------------- layer-1 alpha precompute ----------------
__global__ void k_wa(const float* __restrict__ W1, const float* __restrict__ as1,
                     const float* __restrict__ ad1) {
    int w = (blockIdx.x * blockDim.x + threadIdx.x) >> 5;
    int lane = threadIdx.x & 31;
    if (w >= HEADS1 * 128) return;
    int h = w >> 7, k = w & 127;
    const float* wr = W1 + (size_t)k * HC1 + h * 512;
    const float* sp = as1 + h * 512;
    const float* dp = ad1 + h * 512;
    float s1 = 0.f, s2 = 0.f;
    for (int c = lane; c < 512; c += 32) {
        float wv = wr[c];
        s1 += wv * sp[c];
        s2 += wv * dp[c];
    }
#pragma unroll
    for (int o = 16; o; o >>= 1) {
        s1 += __shfl_down_sync(0xffffffffu, s1, o);
        s2 += __shfl_down_sync(0xffffffffu, s2, o);
    }
    if (lane == 0) {
        g_was[h * 128 + k] = s1;
        g_wad[h * 128 + k] = s2;
    }
}

__global__ void k_alphax(const float* __restrict__ x) {
    int gw = (blockIdx.x * blockDim.x + threadIdx.x) >> 5;
    int lane = threadIdx.x & 31;
    if (gw >= NN * HEADS1) return;
    int n = gw >> 3, h = gw & 7;
    const float* xr = x + (size_t)n * 128;
    const float* ws = g_was + h * 128;
    const float* wd = g_wad + h * 128;
    float s1 = 0.f, s2 = 0.f;
#pragma unroll
    for (int i = 0; i < 4; i++) {
        int k = lane + i * 32;
        float v = xr[k];
        s1 += v * ws[k];
        s2 += v * wd[k];
    }
#pragma unroll
    for (int o = 16; o; o >>= 1) {
        s1 += __shfl_down_sync(0xffffffffu, s1, o);
        s2 += __shfl_down_sync(0xffffffffu, s2, o);
    }
    if (lane == 0) {
        g_as[gw] = s1;
        g_ad[gw] = s2;
    }
}

// ---------------- layer-2: reduce split-K -> h2 fp16, + dots ------------
__global__ void k_alpha2_red(const float* __restrict__ a_s, const float* __restrict__ a_d) {
    int gw = (blockIdx.x * blockDim.x + threadIdx.x) >> 5;
    int lane = threadIdx.x & 31;
    if (gw >= NN) return;
    const float* p = g_gp2 + (size_t)gw * HC2;
    __half* hr = g_h2h + (size_t)gw * HC2;
    float s1 = 0.f, s2 = 0.f;
    for (int c = lane; c < HC2; c += 32) {
        float v = p[c];
#pragma unroll
        for (int z = 1; z < G2_SPLITS; z++) v += p[(size_t)z * NN * HC2 + c];
        hr[c] = __float2half(v);
        s1 += v * a_s[c];
        s2 += v * a_d[c];
    }
#pragma unroll
    for (int o = 16; o; o >>= 1) {
        s1 += __shfl_down_sync(0xffffffffu, s1, o);
        s2 += __shfl_down_sync(0xffffffffu, s2, o);
    }
    if (lane == 0) {
        g_as[gw] = s1;
        g_ad[gw] = s2;
    }
}

// ---------------- fused CSR edge softmax ----------------
template <int H, int NPB>
__global__ void k_softmax() {
    int wid = threadIdx.x >> 5, lane = threadIdx.x & 31;
    int n = blockIdx.x * NPB + wid / H;
    int hd = wid % H;
    int beg = g_rowptr[n], end = g_rowptr[n + 1];
    float adv = g_ad[n * H + hd];

    float mx = -1e30f;
    for (int i = beg + lane; i < end; i += 32) {
        int eid = g_eids[i];
        float v = g_as[g_srcv[eid] * H + hd] + adv;
        v = v > 0.f ? v : 0.2f * v;
        mx = fmaxf(mx, v);
    }
#pragma unroll
    for (int o = 16; o; o >>= 1) mx = fmaxf(mx, __shfl_xor_sync(0xffffffffu, mx, o));

    float s = 0.f;
    for (int i = beg + lane; i < end; i += 32) {
        int eid = g_eids[i];
        float v = g_as[g_srcv[eid] * H + hd] + adv;
        v = v > 0.f ? v : 0.2f * v;
        float e = expf(v - mx);
        g_eexp[eid * H + hd] = e;
        s += e;
    }
#pragma unroll
    for (int o = 16; o; o >>= 1) s += __shfl_xor_sync(0xffffffffu, s, o);
    float inv = 1.f / s;

    for (int i = beg + lane; i < end; i += 32) {
        int eid = g_eids[i];
        g_eexp[eid * H + hd] *= inv;
    }
}

// ---------------- layer-1 CSR aggregate (fp16 h, fp16 out) ----------------
__global__ __launch_bounds__(256) void k_agg1(const float* __restrict__ bias) {
    int n = blockIdx.x, tid = threadIdx.x;
    int c0 = tid * 16, head = tid >> 5;
    int beg = g_rowptr[n], end = g_rowptr[n + 1];
    float acc[16];
#pragma unroll
    for (int j = 0; j < 16; j++) acc[j] = 0.f;

    for (int idx = beg; idx < end; ++idx) {
        int eid = g_eids[idx];
        int src = g_srcv[eid];
        float al = g_eexp[eid * 8 + head];
        const uint4* hp = (const uint4*)(g_h1h + (size_t)src * HC1 + c0);
        uint4 u0 = hp[0], u1 = hp[1];
        unsigned w[8] = {u0.x, u0.y, u0.z, u0.w, u1.x, u1.y, u1.z, u1.w};
#pragma unroll
        for (int j = 0; j < 8; j++) {
            float2 f = __half22float2(*(__half2*)&w[j]);
            acc[2 * j] += al * f.x;
            acc[2 * j + 1] += al * f.y;
        }
    }
    unsigned ow[8];
#pragma unroll
    for (int j = 0; j < 8; j++) {
        float v0 = acc[2 * j] + bias[c0 + 2 * j];
        float v1 = acc[2 * j + 1] + bias[c0 + 2 * j + 1];
        v0 = v0 > 0.f ? v0 : 0.f;
        v1 = v1 > 0.f ? v1 : 0.f;
        __half2 p = __floats2half2_rn(v0, v1);
        ow[j] = *(unsigned*)&p;
    }
    uint4* op = (uint4*)(g_o1h + (size_t)n * HC1 + c0);
    op[0] = make_uint4(ow[0], ow[1], ow[2], ow[3]);
    op[1] = make_uint4(ow[4], ow[5], ow[6], ow[7]);
}

// ---------------- layer-2 CSR aggregate (fp16 h, fp16 out) ----------------
__global__ __launch_bounds__(256) void k_agg2(const float* __restrict__ bias) {
    int n = blockIdx.x, tid = threadIdx.x;
    int c0 = tid * 2;
    int beg = g_rowptr[n], end = g_rowptr[n + 1];
    float a0 = 0.f, a1 = 0.f;
    for (int idx = beg; idx < end; ++idx) {
        int eid = g_eids[idx];
        int src = g_srcv[eid];
        float al = g_eexp[eid];
        float2 f = __half22float2(*(const __half2*)(g_h2h + (size_t)src * HC2 + c0));
        a0 += al * f.x;
        a1 += al * f.y;
    }
    float v0 = a0 + bias[c0], v1 = a1 + bias[c0 + 1];
    v0 = v0 > 0.f ? v0 : 0.f;
    v1 = v1 > 0.f ? v1 : 0.f;
    *(__half2*)(g_o2h + (size_t)n * HC2 + c0) = __floats2half2_rn(v0, v1);
}

// ---------------- fc3 ----------------
__global__ void k_fc3(int Atag, const float* __restrict__ W,
                      const float* __restrict__ b, float* __restrict__ out) {
    const float* A = bufptr(Atag);
    int i = blockIdx.x * blockDim.x + threadIdx.x;
    if (i >= 512 * 10) return;
    int m = i / 10, n = i - m * 10;
    float s = b[n];
#pragma unroll 8
    for (int k = 0; k < 128; k++) s += A[m * 128 + k] * W[k * 10 + n];
    out[i] = s;
}

extern "C" void kernel_launch(void* const* d_in, const int* in_sizes, int n_in,
                              void* d_out, int out_size) {
    const float* x = (const float*)d_in[0];
    const int* ei_raw = (const int*)d_in[1];
    const float* W1 = (const float*)d_in[3];
    const float* as1 = (const float*)d_in[4];
    const float* ad1 = (const float*)d_in[5];
    const float* b1 = (const float*)d_in[6];
    const float* W2 = (const float*)d_in[7];
    const float* as2 = (const float*)d_in[8];
    const float* ad2 = (const float*)d_in[9];
    const float* b2 = (const float*)d_in[10];
    const float* fc1w = (const float*)d_in[11];
    const float* fc1b = (const float*)d_in[12];
    const float* fc2w = (const float*)d_in[13];
    const float* fc2b = (const float*)d_in[14];
    const float* fc3w = (const float*)d_in[15];
    const float* fc3b = (const float*)d_in[16];
    float* out = (float*)d_out;

    // ---- fused CSR build + merged converts ----
    k_graph<<<1, 1024>>>(ei_raw);
    k_cvt_all<<<(CVT_TOT / 16 + 255) / 256, 256>>>(x, W1, W2, fc1w);
    k_wa<<<(HEADS1 * 128) / 8, 256>>>(W1, as1, ad1);

    // ---- layer 1 ----
    k_mm_h<true><<<dim3(HC1 / 128, NN / 128, 1), 128>>>(H_XH, H_W1, H_H1, NN, HC1, 128,
                                                        128, HC1);
    k_alphax<<<(NN * HEADS1) / 8, 256>>>(x);
    k_softmax<HEADS1, 1><<<NN, 256>>>();
    k_agg1<<<NN, 256>>>(b1);

    // ---- layer 2: split-K=4 ----
    k_mm_h<false><<<dim3(HC2 / 128, NN / 128, G2_SPLITS), 128>>>(
        H_O1, H_W2, B_GP2, NN, HC2, HC1 / G2_SPLITS, HC1, HC2);
    k_alpha2_red<<<(NN * 32 + 255) / 256, 256>>>(as2, ad2);
    k_softmax<1, 8><<<NN / 8, 256>>>();
    k_agg2<<<NN, 256>>>(b2);

    // ---- MLP head ----
    k_mm_h<false><<<dim3(512 / 128, 512 / 128, FC1_SPLITS), 128>>>(
        H_O2, H_FW, B_FCP, 512, 512, HC1 / FC1_SPLITS, HC1, 512);
    k_fcreduce<<<(512 * 512 + 255) / 256, 256>>>(fc1b);
    k_gemm64<true><<<dim3(128 / 64, 512 / 64), 256>>>(B_FC1, fc2w, fc2b, B_FC2, 512, 128, 512);
    k_fc3<<<(512 * 10 + 255) / 256, 256>>>(B_FC2, fc3w, fc3b, out);
}